// round 1
// baseline (speedup 1.0000x reference)
#include <cuda_runtime.h>

#define BB 8
#define CI 128
#define MC 64
#define HH 64
#define WW 64
#define NH 128
#define NW 128
#define NO 100
#define KK2 25
#define MW2 68   // m_s padded row width (kernel 2)
#define XW3 68   // x_s padded row width (kernel 3)
#define CC3 16   // channel chunk (kernel 3)
#define CP3 18   // padded channel stride (kernel 3)

// Scratch (allocation-free per harness rules)
__device__ float g_m[BB * MC * HH * WW];        // 8 MB
__device__ float g_ker[BB * KK2 * NH * NW];     // 13.1 MB

typedef unsigned long long u64;

__device__ __forceinline__ u64 pk2(float lo, float hi) {
    u64 r; asm("mov.b64 %0, {%1,%2};" : "=l"(r) : "f"(lo), "f"(hi)); return r;
}
__device__ __forceinline__ float2 upk2(u64 v) {
    float2 f; asm("mov.b64 {%0,%1}, %2;" : "=f"(f.x), "=f"(f.y) : "l"(v)); return f;
}
// packed f32x2 FMA: 2 FMAs per issue slot (sm_100+ only, never emitted by ptxas from C++)
__device__ __forceinline__ void fma2(u64 &acc, u64 a, u64 b) {
    asm("fma.rn.f32x2 %0, %1, %2, %0;" : "+l"(acc) : "l"(a), "l"(b));
}
__device__ __forceinline__ u64 ld2(const float* p) {
    return *reinterpret_cast<const u64*>(p);
}

// ---------------------------------------------------------------------------
// Kernel 1: 1x1 compress conv  x(B,128,H,W) -> m(B,64,H,W)
// block = (h,b), 256 thr. x row transposed into smem [w][c] so channel pairs
// are contiguous for f32x2; each thread computes 4 m-channels for one w.
// ---------------------------------------------------------------------------
__global__ __launch_bounds__(256)
void k_compress(const float* __restrict__ x, const float* __restrict__ cw,
                const float* __restrict__ cb) {
    __shared__ __align__(16) float xs[64][130];  // [w][c], pad 130 for banks
    const int h = blockIdx.x, b = blockIdx.y, tid = threadIdx.x;
    const float* xb = x + ((size_t)b * CI * HH + h) * WW;
    for (int idx = tid; idx < CI * WW; idx += 256) {
        int c = idx >> 6, w = idx & 63;
        xs[w][c] = xb[(size_t)c * HH * WW + w];
    }
    __syncthreads();
    #pragma unroll
    for (int it = 0; it < 4; ++it) {
        int task = it * 256 + tid;
        int w = task & 63, mg = task >> 6;
        int mm0 = mg * 4;
        u64 a0 = 0, a1 = 0, a2 = 0, a3 = 0;
        const float* cwp = cw + (size_t)mm0 * CI;
        const float* xr = xs[w];
        #pragma unroll 4
        for (int c = 0; c < CI; c += 2) {
            u64 xv = ld2(xr + c);
            fma2(a0, xv, ld2(cwp + c));
            fma2(a1, xv, ld2(cwp + CI + c));
            fma2(a2, xv, ld2(cwp + 2 * CI + c));
            fma2(a3, xv, ld2(cwp + 3 * CI + c));
        }
        float2 r0 = upk2(a0), r1 = upk2(a1), r2 = upk2(a2), r3 = upk2(a3);
        float* mp = g_m + (((size_t)b * MC + mm0) * HH + h) * WW + w;
        mp[0]           = r0.x + r0.y + cb[mm0];
        mp[HH * WW]     = r1.x + r1.y + cb[mm0 + 1];
        mp[2 * HH * WW] = r2.x + r2.y + cb[mm0 + 2];
        mp[3 * HH * WW] = r3.x + r3.y + cb[mm0 + 3];
    }
}

// ---------------------------------------------------------------------------
// Kernel 2: 3x3 encoder conv (64->100 ch) + bias + pixel-shuffle + softmax(25)
// block = (h,b), 320 thr. m rows h-1..h+1 staged in smem with zero halo.
// Conv: 800 tasks (100 o x 8 w-groups), thread computes 8 outputs via 4
// packed f32x2 accumulators. Then softmax per (subpixel, w) over 25 taps.
// ---------------------------------------------------------------------------
extern __shared__ float smem2[];
__global__ __launch_bounds__(320)
void k_encoder(const float* __restrict__ ew, const float* __restrict__ eb) {
    float* m_s = smem2;                 // [c][r][MW2], index = (c*3+r)*68 + (w+1)
    float* kt  = smem2 + MC * 3 * MW2;  // [o][64]
    const int h = blockIdx.x, b = blockIdx.y, tid = threadIdx.x;

    for (int idx = tid; idx < MC * 3 * MW2; idx += 320) {
        int c = idx / (3 * MW2); int rem = idx - c * 3 * MW2;
        int r = rem / MW2; int wi = rem - r * MW2;
        int hh = h + r - 1, w = wi - 1;
        float v = 0.f;
        if (hh >= 0 && hh < HH && (unsigned)w < WW)
            v = g_m[(((size_t)b * MC + c) * HH + hh) * WW + w];
        m_s[idx] = v;
    }
    __syncthreads();

    for (int it = 0; it < 3; ++it) {
        int task = it * 320 + tid;
        if (task < 800) {
            int o = task >> 3, wg = task & 7;
            int w0 = wg * 8;
            float bias = __ldg(eb + o);
            u64 bb = pk2(bias, bias);
            u64 aA = bb, aB = bb, aC = bb, aD = bb;
            const float* wp = ew + (size_t)o * MC * 9;
            #pragma unroll 2
            for (int c = 0; c < MC; c++) {
                const float* mr = m_s + (c * 3) * MW2 + w0;
                const float* wc = wp + c * 9;
                #pragma unroll
                for (int r = 0; r < 3; r++) {
                    const float4 v0 = *reinterpret_cast<const float4*>(mr + r * MW2);
                    const float4 v1 = *reinterpret_cast<const float4*>(mr + r * MW2 + 4);
                    const float2 v2 = *reinterpret_cast<const float2*>(mr + r * MW2 + 8);
                    float wa = wc[r * 3 + 0], wb = wc[r * 3 + 1], wcv = wc[r * 3 + 2];
                    u64 s0 = pk2(wa, wa), s1 = pk2(wb, wb), s2 = pk2(wcv, wcv);
                    u64 P0 = pk2(v0.x, v0.y), P1 = pk2(v0.y, v0.z), P2 = pk2(v0.z, v0.w);
                    u64 P3 = pk2(v0.w, v1.x), P4 = pk2(v1.x, v1.y), P5 = pk2(v1.y, v1.z);
                    u64 P6 = pk2(v1.z, v1.w), P7 = pk2(v1.w, v2.x), P8 = pk2(v2.x, v2.y);
                    fma2(aA, P0, s0); fma2(aB, P2, s0); fma2(aC, P4, s0); fma2(aD, P6, s0);
                    fma2(aA, P1, s1); fma2(aB, P3, s1); fma2(aC, P5, s1); fma2(aD, P7, s1);
                    fma2(aA, P2, s2); fma2(aB, P4, s2); fma2(aC, P6, s2); fma2(aD, P8, s2);
                }
            }
            float* kp = kt + o * 64 + w0;
            float2 rA = upk2(aA), rB = upk2(aB), rC = upk2(aC), rD = upk2(aD);
            kp[0] = rA.x; kp[1] = rA.y; kp[2] = rB.x; kp[3] = rB.y;
            kp[4] = rC.x; kp[5] = rC.y; kp[6] = rD.x; kp[7] = rD.y;
        }
    }
    __syncthreads();

    // softmax over 25 taps per (subpixel, w); channel n = kk*4 + sh*2 + sw
    if (tid < 256) {
        int sub = tid >> 6, w = tid & 63;
        int sh = sub >> 1, sw = sub & 1;
        float v[25]; float mx = -1e30f;
        #pragma unroll
        for (int t = 0; t < 25; t++) { v[t] = kt[(t * 4 + sub) * 64 + w]; mx = fmaxf(mx, v[t]); }
        float s = 0.f;
        #pragma unroll
        for (int t = 0; t < 25; t++) { v[t] = __expf(v[t] - mx); s += v[t]; }
        float inv = 1.f / s;
        int oh = 2 * h + sh, ow = 2 * w + sw;
        #pragma unroll
        for (int t = 0; t < 25; t++)
            g_ker[(((size_t)b * KK2 + t) * NH + oh) * NW + ow] = v[t] * inv;
    }
}

// ---------------------------------------------------------------------------
// Kernel 3: out[b,c,oh,ow] = sum_{i,j} x[b,c,h+i-2,w+j-2] * ker[b,i*5+j,oh,ow]
// block = (oh,b), 256 thr. ker row in smem; x staged channel-chunked (16) in
// c-minor layout so channel pairs feed f32x2; weight splatted across pair.
// ---------------------------------------------------------------------------
__global__ __launch_bounds__(256)
void k_carafe(const float* __restrict__ x, float* __restrict__ out) {
    __shared__ float ker_s[KK2 * 128];
    __shared__ __align__(16) float x_s[5 * XW3 * CP3];  // [i][iw][c], iw = xcol+2
    const int oh = blockIdx.x, b = blockIdx.y, tid = threadIdx.x;
    const int h = oh >> 1;
    for (int idx = tid; idx < KK2 * 128; idx += 256)
        ker_s[idx] = g_ker[(((size_t)b * KK2 + (idx >> 7)) * NH + oh) * NW + (idx & 127)];
    const int ow = tid & 127, chalf = tid >> 7;
    const int w = ow >> 1;
    for (int c0 = 0; c0 < CI; c0 += CC3) {
        __syncthreads();
        for (int idx = tid; idx < 5 * XW3 * CC3; idx += 256) {
            int iw = idx % XW3; int t2 = idx / XW3;
            int i = t2 % 5; int cc = t2 / 5;
            int row = h + i - 2, col = iw - 2;
            float v = 0.f;
            if ((unsigned)row < HH && (unsigned)col < WW)
                v = x[(((size_t)b * CI + c0 + cc) * HH + row) * WW + col];
            x_s[(i * XW3 + iw) * CP3 + cc] = v;
        }
        __syncthreads();
        u64 a0 = 0, a1 = 0, a2 = 0, a3 = 0;
        #pragma unroll
        for (int t = 0; t < 25; t++) {
            int i = t / 5, j = t - i * 5;
            float kv = ker_s[t * 128 + ow];
            u64 ks = pk2(kv, kv);
            const float* xb = x_s + (i * XW3 + (w + j)) * CP3 + chalf * 8;
            fma2(a0, ld2(xb + 0), ks);
            fma2(a1, ld2(xb + 2), ks);
            fma2(a2, ld2(xb + 4), ks);
            fma2(a3, ld2(xb + 6), ks);
        }
        float* ob = out + (((size_t)b * CI + c0 + chalf * 8) * NH + oh) * NW + ow;
        float2 r0 = upk2(a0), r1 = upk2(a1), r2 = upk2(a2), r3 = upk2(a3);
        const size_t P = (size_t)NH * NW;
        ob[0] = r0.x;     ob[P] = r0.y;
        ob[2 * P] = r1.x; ob[3 * P] = r1.y;
        ob[4 * P] = r2.x; ob[5 * P] = r2.y;
        ob[6 * P] = r3.x; ob[7 * P] = r3.y;
    }
}

// ---------------------------------------------------------------------------
extern "C" void kernel_launch(void* const* d_in, const int* in_sizes, int n_in,
                              void* d_out, int out_size) {
    const float* x  = (const float*)d_in[0];
    const float* cw = (const float*)d_in[1];
    const float* cb = (const float*)d_in[2];
    const float* ew = (const float*)d_in[3];
    const float* eb = (const float*)d_in[4];
    float* out = (float*)d_out;

    const int smem2 = (MC * 3 * MW2 + NO * 64) * (int)sizeof(float);  // ~76 KB
    cudaFuncSetAttribute(k_encoder, cudaFuncAttributeMaxDynamicSharedMemorySize, smem2);

    k_compress<<<dim3(HH, BB), 256>>>(x, cw, cb);
    k_encoder<<<dim3(HH, BB), 320, smem2>>>(ew, eb);
    k_carafe<<<dim3(NH, BB), 256>>>(x, out);
}

// round 2
// speedup vs baseline: 1.2817x; 1.2817x over previous
#include <cuda_runtime.h>

#define BB 8
#define CI 128
#define MC 64
#define HH 64
#define WW 64
#define NH 128
#define NW 128

// Scratch (allocation-free per harness rules)
__device__ float g_m[BB * MC * HH * WW];      // compressed features
__device__ float g_ker[BB * 25 * NH * NW];    // softmax kernels
__device__ float g_ew2[128 * 9 * 64];         // encoder weights [o][tap][c], o padded to 128

typedef unsigned long long u64;

__device__ __forceinline__ u64 pk2(float lo, float hi) {
    u64 r; asm("mov.b64 %0, {%1,%2};" : "=l"(r) : "f"(lo), "f"(hi)); return r;
}
__device__ __forceinline__ float2 upk2(u64 v) {
    float2 f; asm("mov.b64 {%0,%1}, %2;" : "=f"(f.x), "=f"(f.y) : "l"(v)); return f;
}
__device__ __forceinline__ void fma2(u64 &acc, u64 a, u64 b) {
    asm("fma.rn.f32x2 %0, %1, %2, %0;" : "+l"(acc) : "l"(a), "l"(b));
}

// ---------------------------------------------------------------------------
// Prep: transpose encoder weights (o,c,3,3) -> [o][tap][c], zero-pad o to 128
// ---------------------------------------------------------------------------
__global__ __launch_bounds__(256)
void k_prep(const float* __restrict__ ew) {
    int idx = blockIdx.x * 256 + threadIdx.x;   // over 128*9*64 = 73728
    if (idx >= 128 * 9 * 64) return;
    int c = idx & 63, tap = (idx >> 6) % 9, o = idx / 576;
    g_ew2[idx] = (o < 100) ? ew[o * 576 + c * 9 + tap] : 0.f;
}

// ---------------------------------------------------------------------------
// Kernel 1: 1x1 compress conv. block=(h,b), 256 thr.
// x row -> smem [w][c] (XOR-swizzled quads), weights -> smem [m][c].
// Thread: 16 m-channels for one w; weights via broadcast LDS.128.
// ---------------------------------------------------------------------------
extern __shared__ float sm1[];
__global__ __launch_bounds__(256)
void k_compress(const float* __restrict__ x, const float* __restrict__ cw,
                const float* __restrict__ cb) {
    float* xs = sm1;              // 64*128 floats, swizzled [w][c]
    float* ws = sm1 + 64 * 128;   // 64*128 floats, plain [m][c]
    const int h = blockIdx.x, b = blockIdx.y, tid = threadIdx.x;
    const float* xb = x + ((size_t)b * CI * HH + h) * WW;

    // stage x: per (c, w-quad) read float4 from gmem, scatter with swizzle
    for (int idx = tid; idx < CI * 16; idx += 256) {
        int w0 = (idx & 15) * 4, c = idx >> 4;
        float4 v = *reinterpret_cast<const float4*>(xb + (size_t)c * HH * WW + w0);
        int cq = c >> 2, cl = c & 3;
        float vv[4] = {v.x, v.y, v.z, v.w};
        #pragma unroll
        for (int k = 0; k < 4; k++) {
            int w = w0 + k;
            xs[(w << 7) + ((cq ^ (w & 7)) << 2) + cl] = vv[k];
        }
    }
    // stage weights (vectorized)
    for (int idx = tid; idx < MC * CI / 4; idx += 256)
        reinterpret_cast<float4*>(ws)[idx] = reinterpret_cast<const float4*>(cw)[idx];
    __syncthreads();

    const int w = tid & 63, mt = tid >> 6;   // mt: 0..3 -> 16 m each
    u64 acc[16];
    #pragma unroll
    for (int i = 0; i < 16; i++) acc[i] = 0;
    const float* xrow = xs + (w << 7);
    const float* wb = ws + mt * 16 * CI;
    const int wx = w & 7;
    #pragma unroll
    for (int cq = 0; cq < 32; cq++) {
        float4 xq = *reinterpret_cast<const float4*>(xrow + ((cq ^ wx) << 2));
        u64 xlo = pk2(xq.x, xq.y), xhi = pk2(xq.z, xq.w);
        #pragma unroll
        for (int mm = 0; mm < 16; mm++) {
            float4 wq = *reinterpret_cast<const float4*>(wb + mm * CI + (cq << 2));
            fma2(acc[mm], xlo, pk2(wq.x, wq.y));
            fma2(acc[mm], xhi, pk2(wq.z, wq.w));
        }
    }
    #pragma unroll
    for (int mm = 0; mm < 16; mm++) {
        int m = mt * 16 + mm;
        float2 r = upk2(acc[mm]);
        g_m[(((size_t)b * MC + m) * HH + h) * WW + w] = r.x + r.y + cb[m];
    }
}

// ---------------------------------------------------------------------------
// Kernel 2: 3x3 encoder conv (64->100) + bias + pixel-shuffle + softmax(25).
// block=(h,b), 256 thr. m halo rows in smem (c-minor, swizzled). Weights in
// smem chunks of 32 o. Warp = (w-half, 8-o tile); all hot-loop operands LDS.
// ---------------------------------------------------------------------------
extern __shared__ float sm2[];
__global__ __launch_bounds__(256)
void k_encoder(const float* __restrict__ eb) {
    float* m_s = sm2;                      // 3*66*64 = 12672 floats
    float* wsm = sm2 + 12672;              // 32*576  = 18432 floats
    float* kt  = sm2 + 12672 + 18432;      // 100*64  = 6400 floats
    const int h = blockIdx.x, b = blockIdx.y, tid = threadIdx.x;

    // stage m halo: [r][iw][c] swizzled, zero-padded borders
    for (int idx = tid; idx < 3 * 66 * 64; idx += 256) {
        int iw = idx % 66; int t2 = idx / 66; int r = t2 % 3; int c = t2 / 3;
        int hh = h + r - 1, ww = iw - 1;
        float v = 0.f;
        if ((unsigned)hh < HH && (unsigned)ww < WW)
            v = g_m[(((size_t)b * MC + c) * HH + hh) * WW + ww];
        int cq = c >> 2, cl = c & 3;
        m_s[((r * 66 + iw) << 6) + ((cq ^ (iw & 7)) << 2) + cl] = v;
    }

    const int wid = tid >> 5, lane = tid & 31;
    const int whalf = wid & 1, otile = wid >> 1;   // otile 0..3
    const int w = whalf * 32 + lane;

    for (int oc = 0; oc < 4; oc++) {
        __syncthreads();
        for (int idx = tid; idx < 32 * 576 / 4; idx += 256)
            reinterpret_cast<float4*>(wsm)[idx] =
                reinterpret_cast<const float4*>(g_ew2 + oc * 32 * 576)[idx];
        __syncthreads();

        const int ob = otile * 8;
        u64 acc[8];
        #pragma unroll
        for (int oo = 0; oo < 8; oo++) {
            int o = oc * 32 + ob + oo;
            acc[oo] = pk2(o < 100 ? __ldg(eb + o) : 0.f, 0.f);
        }
        #pragma unroll 1
        for (int r = 0; r < 3; r++) {
            #pragma unroll 1
            for (int s = 0; s < 3; s++) {
                const float* xrow = m_s + ((r * 66 + w + s) << 6);
                const int ixw = (w + s) & 7;
                const float* wt = wsm + ((ob * 9 + r * 3 + s) << 6);
                #pragma unroll
                for (int cq = 0; cq < 16; cq++) {
                    float4 xq = *reinterpret_cast<const float4*>(xrow + ((cq ^ ixw) << 2));
                    u64 xlo = pk2(xq.x, xq.y), xhi = pk2(xq.z, xq.w);
                    #pragma unroll
                    for (int oo = 0; oo < 8; oo++) {
                        float4 wq = *reinterpret_cast<const float4*>(
                            wt + ((oo * 9) << 6) + (cq << 2));
                        fma2(acc[oo], xlo, pk2(wq.x, wq.y));
                        fma2(acc[oo], xhi, pk2(wq.z, wq.w));
                    }
                }
            }
        }
        #pragma unroll
        for (int oo = 0; oo < 8; oo++) {
            int o = oc * 32 + ob + oo;
            if (o < 100) { float2 r2 = upk2(acc[oo]); kt[o * 64 + w] = r2.x + r2.y; }
        }
    }
    __syncthreads();

    // softmax over 25 taps; channel n = t*4 + sh*2 + sw
    {
        int sub = tid >> 6, w2 = tid & 63;
        int sh = sub >> 1, sw = sub & 1;
        float v[25]; float mx = -1e30f;
        #pragma unroll
        for (int t = 0; t < 25; t++) { v[t] = kt[(t * 4 + sub) * 64 + w2]; mx = fmaxf(mx, v[t]); }
        float ssum = 0.f;
        #pragma unroll
        for (int t = 0; t < 25; t++) { v[t] = __expf(v[t] - mx); ssum += v[t]; }
        float inv = 1.f / ssum;
        int oh = 2 * h + sh, ow = 2 * w2 + sw;
        #pragma unroll
        for (int t = 0; t < 25; t++)
            g_ker[(((size_t)b * 25 + t) * NH + oh) * NW + ow] = v[t] * inv;
    }
}

// ---------------------------------------------------------------------------
// Kernel 3: content-aware reassembly. block=(h,b) covers BOTH output rows
// (2h, 2h+1); thread = (w, c-oct) covers ow-pair (2w, 2w+1) so each x quad
// feeds 8 fma2 (2 oh x 2 ow x 2 c-pairs).
// ---------------------------------------------------------------------------
extern __shared__ float sm3[];
__global__ __launch_bounds__(256)
void k_carafe(const float* __restrict__ x, float* __restrict__ out) {
    float* ker_s = sm3;           // [t][p][128] = 6400 floats
    float* x_s   = sm3 + 6400;    // 5*68*32 = 10880 floats, swizzled
    const int h = blockIdx.x, b = blockIdx.y, tid = threadIdx.x;

    for (int idx = tid; idx < 25 * 2 * 128; idx += 256) {
        int ow = idx & 127; int t2 = idx >> 7; int p = t2 & 1; int t = t2 >> 1;
        ker_s[idx] = g_ker[(((size_t)b * 25 + t) * NH + 2 * h + p) * NW + ow];
    }
    const int w = tid & 63, co = tid >> 6;   // co: 0..3 -> 8 channels

    for (int c0 = 0; c0 < CI; c0 += 32) {
        __syncthreads();
        for (int idx = tid; idx < 5 * 68 * 32; idx += 256) {
            int iw = idx % 68; int t2 = idx / 68; int i = t2 % 5; int cc = t2 / 5;
            int row = h + i - 2, col = iw - 2;
            float v = 0.f;
            if ((unsigned)row < HH && (unsigned)col < WW)
                v = x[(((size_t)b * CI + c0 + cc) * HH + row) * WW + col];
            int cq = cc >> 2, cl = cc & 3;
            x_s[((i * 68 + iw) << 5) + ((cq ^ (iw & 7)) << 2) + cl] = v;
        }
        __syncthreads();

        u64 acc[4][4];   // [p*2+q][c-pair]
        #pragma unroll
        for (int a = 0; a < 4; a++)
            #pragma unroll
            for (int p = 0; p < 4; p++) acc[a][p] = 0;

        #pragma unroll 1
        for (int i = 0; i < 5; i++) {
            #pragma unroll
            for (int j = 0; j < 5; j++) {
                int t = i * 5 + j;
                int iw = w + j;
                const float* xr = x_s + ((i * 68 + iw) << 5);
                int sw8 = iw & 7;
                float4 xa = *reinterpret_cast<const float4*>(xr + (((co * 2) ^ sw8) << 2));
                float4 xc = *reinterpret_cast<const float4*>(xr + (((co * 2 + 1) ^ sw8) << 2));
                u64 X0 = pk2(xa.x, xa.y), X1 = pk2(xa.z, xa.w);
                u64 X2 = pk2(xc.x, xc.y), X3 = pk2(xc.z, xc.w);
                float2 k0 = *reinterpret_cast<const float2*>(ker_s + (t * 2 + 0) * 128 + 2 * w);
                float2 k1 = *reinterpret_cast<const float2*>(ker_s + (t * 2 + 1) * 128 + 2 * w);
                u64 K00 = pk2(k0.x, k0.x), K01 = pk2(k0.y, k0.y);
                u64 K10 = pk2(k1.x, k1.x), K11 = pk2(k1.y, k1.y);
                fma2(acc[0][0], X0, K00); fma2(acc[0][1], X1, K00);
                fma2(acc[0][2], X2, K00); fma2(acc[0][3], X3, K00);
                fma2(acc[1][0], X0, K01); fma2(acc[1][1], X1, K01);
                fma2(acc[1][2], X2, K01); fma2(acc[1][3], X3, K01);
                fma2(acc[2][0], X0, K10); fma2(acc[2][1], X1, K10);
                fma2(acc[2][2], X2, K10); fma2(acc[2][3], X3, K10);
                fma2(acc[3][0], X0, K11); fma2(acc[3][1], X1, K11);
                fma2(acc[3][2], X2, K11); fma2(acc[3][3], X3, K11);
            }
        }
        // writeback: STG.64 over ow-pair per (channel, oh)
        #pragma unroll
        for (int p = 0; p < 2; p++) {
            #pragma unroll
            for (int cp = 0; cp < 4; cp++) {
                float2 rA = upk2(acc[p * 2 + 0][cp]);   // q=0: channels (c, c+1)
                float2 rB = upk2(acc[p * 2 + 1][cp]);   // q=1
                int c = c0 + co * 8 + cp * 2;
                size_t base = (((size_t)b * CI + c) * NH + 2 * h + p) * NW + 2 * w;
                *reinterpret_cast<float2*>(out + base) = make_float2(rA.x, rB.x);
                *reinterpret_cast<float2*>(out + base + (size_t)NH * NW) = make_float2(rA.y, rB.y);
            }
        }
    }
}

// ---------------------------------------------------------------------------
extern "C" void kernel_launch(void* const* d_in, const int* in_sizes, int n_in,
                              void* d_out, int out_size) {
    const float* x  = (const float*)d_in[0];
    const float* cw = (const float*)d_in[1];
    const float* cb = (const float*)d_in[2];
    const float* ew = (const float*)d_in[3];
    const float* eb = (const float*)d_in[4];
    float* out = (float*)d_out;

    static int inited = 0;
    if (!inited) {
        cudaFuncSetAttribute(k_compress, cudaFuncAttributeMaxDynamicSharedMemorySize, 65536);
        cudaFuncSetAttribute(k_encoder,  cudaFuncAttributeMaxDynamicSharedMemorySize, 150016);
        cudaFuncSetAttribute(k_carafe,   cudaFuncAttributeMaxDynamicSharedMemorySize, 69120);
        inited = 1;
    }

    k_prep<<<288, 256>>>(ew);
    k_compress<<<dim3(HH, BB), 256, 65536>>>(x, cw, cb);
    k_encoder<<<dim3(HH, BB), 256, 150016>>>(eb);
    k_carafe<<<dim3(HH, BB), 256, 69120>>>(x, out);
}